// round 14
// baseline (speedup 1.0000x reference)
#include <cuda_runtime.h>

#define T_    16384
#define TILE  128              // elements per warp-tile (4 per lane)
#define SPAN  1024             // output elements per warp
#define SPANS (T_ / SPAN)      // 16 warps per row
#define MT    (SPAN / TILE)    // 8 main tiles per warp
#define WPC   4
#define FULL  0xffffffffu

struct Ser { float b, w1, w2, w3, w4, w5, w6, pw; };

__device__ __forceinline__ Ser make_ser(float b, int lane) {
    Ser s; s.b = b;
    float b2 = b * b;
    s.w1 = b2 * b2;          // b^4   (lane-segment weight)
    s.w2 = s.w1 * s.w1;      // b^8
    s.w3 = s.w2 * s.w2;      // b^16
    s.w4 = s.w3 * s.w3;      // b^32
    s.w5 = s.w4 * s.w4;      // b^64
    s.w6 = s.w5 * s.w5;      // b^128 (whole-tile carry weight)
    float pw = 1.f, p = s.w1;
#pragma unroll
    for (int k = 0; k < 5; ++k) { if (lane & (1 << k)) pw *= p; p *= p; }
    s.pw = pw;               // b^(4*lane)
    return s;
}

// Compose + Kogge-Stone over a 128-elt tile (4 per lane).
__device__ __forceinline__ void ksphase(const Ser s, const float4 v,
                                        float& sb, float& tot, int lane)
{
    float Bv = fmaf(s.b, fmaf(s.b, fmaf(s.b, v.x, v.y), v.z), v.w);
    float t;
    t = __shfl_up_sync(FULL, Bv, 1);  if (lane >= 1)  Bv = fmaf(s.w1, t, Bv);
    t = __shfl_up_sync(FULL, Bv, 2);  if (lane >= 2)  Bv = fmaf(s.w2, t, Bv);
    t = __shfl_up_sync(FULL, Bv, 4);  if (lane >= 4)  Bv = fmaf(s.w3, t, Bv);
    t = __shfl_up_sync(FULL, Bv, 8);  if (lane >= 8)  Bv = fmaf(s.w4, t, Bv);
    t = __shfl_up_sync(FULL, Bv, 16); if (lane >= 16) Bv = fmaf(s.w5, t, Bv);
    sb  = __shfl_up_sync(FULL, Bv, 1);
    tot = __shfl_sync(FULL, Bv, 31);
    if (lane == 0) sb = 0.f;
}

// Carry-only variant (warmup): tot only.
__device__ __forceinline__ float kstot(const Ser s, const float4 v, int lane)
{
    float Bv = fmaf(s.b, fmaf(s.b, fmaf(s.b, v.x, v.y), v.z), v.w);
    float t;
    t = __shfl_up_sync(FULL, Bv, 1);  if (lane >= 1)  Bv = fmaf(s.w1, t, Bv);
    t = __shfl_up_sync(FULL, Bv, 2);  if (lane >= 2)  Bv = fmaf(s.w2, t, Bv);
    t = __shfl_up_sync(FULL, Bv, 4);  if (lane >= 4)  Bv = fmaf(s.w3, t, Bv);
    t = __shfl_up_sync(FULL, Bv, 8);  if (lane >= 8)  Bv = fmaf(s.w4, t, Bv);
    t = __shfl_up_sync(FULL, Bv, 16); if (lane >= 16) Bv = fmaf(s.w5, t, Bv);
    return __shfl_sync(FULL, Bv, 31);
}

// One reconstruct step: advance es/el/eg by x, emit m and g.
#define RSTEP(xvj, m, g) do {                                      \
    es = fmaf(b_s, es, (xvj));                                     \
    el = fmaf(b_l, el, (xvj));                                     \
    eg = fmaf(b_g, eg, (xvj));                                     \
    (m) = fmaf(a_s, es, -(a_l * el));                              \
    (g) = fmaf(K_s, es, fmaf(K_l, el, K_g * eg));                  \
} while (0)

__global__ __launch_bounds__(32 * WPC)
void macd_scan(const float* __restrict__ x,
               const int* __restrict__ ps_, const int* __restrict__ pl_,
               const int* __restrict__ pg_,
               float* __restrict__ out, int B)
{
    const int lane = threadIdx.x & 31;
    const int w    = blockIdx.x * WPC + (threadIdx.x >> 5);
    const int row  = w / SPANS;
    const int span = w - row * SPANS;
    if (row >= B) return;

    const float a_s = 2.f / (float)(ps_[0] + 1), b_s = 1.f - a_s;
    const float a_l = 2.f / (float)(pl_[0] + 1), b_l = 1.f - a_l;
    const float a_g = 2.f / (float)(pg_[0] + 1), b_g = 1.f - a_g;
    const Ser ss = make_ser(b_s, lane);
    const Ser sl = make_ser(b_l, lane);
    const Ser sg = make_ser(b_g, lane);

    // Partial fractions (validated R10): macd = a_s*Fs - a_l*Fl,
    // sig = Ks*Fs + Kl*Fl + Kg*Fg, with F = unnormalized EMAs of raw x.
    const float r_s = __fdividef(1.f, b_g - b_s);
    const float r_l = __fdividef(1.f, b_g - b_l);
    const float K_s = -a_g * a_s * b_s * r_s;
    const float K_l =  a_g * a_l * b_l * r_l;
    const float K_g =  a_g * b_g * (a_s * r_s - a_l * r_l);
    const float inv_as = __fdividef(1.f, a_s);
    const float inv_al = __fdividef(1.f, a_l);
    const float sg_c   = __fdividef(b_s * r_s - b_l * r_l,
                                    b_g * (a_s * r_s - a_l * r_l));

    const size_t rbase = (size_t)row * T_;
    const int    off0  = span * SPAN;
    const size_t N     = (size_t)B * T_;
    const float* __restrict__ xp = x + rbase;
    float* __restrict__ om = out;
    float* __restrict__ og = out + N;
    float* __restrict__ oh = out + 2 * N;

    float Ss, Sl, Sg;

    if (span == 0) {
        const float x0 = __ldg(xp);
        Ss = x0 * inv_as; Sl = x0 * inv_al; Sg = x0 * sg_c;
    } else {
        // Self-start warmup: two carry-only tiles over [off0-256, off0).
        const float4 wa = *(const float4*)(xp + (off0 - 2 * TILE) + lane * 4);
        const float4 wb = *(const float4*)(xp + (off0 - TILE)     + lane * 4);
        const float x0 = __shfl_sync(FULL, wa.x, 0);
        Ss = x0 * inv_as; Sl = x0 * inv_al; Sg = x0 * sg_c;
        Ss = fmaf(ss.w6, Ss, kstot(ss, wa, lane));
        Sl = fmaf(sl.w6, Sl, kstot(sl, wa, lane));
        Sg = fmaf(sg.w6, Sg, kstot(sg, wa, lane));
        Ss = fmaf(ss.w6, Ss, kstot(ss, wb, lane));
        Sl = fmaf(sl.w6, Sl, kstot(sl, wb, lane));
        Sg = fmaf(sg.w6, Sg, kstot(sg, wb, lane));
    }

#pragma unroll 4
    for (int t = 0; t < MT; ++t) {
        const size_t base = rbase + (size_t)off0 + t * TILE + lane * 4;
        const float4 v = *(const float4*)(x + base);

        // Three independent KS phases (shfl chains interleave 3-wide).
        float sbs, tots, sbl, totl, sbg, totg;
        ksphase(ss, v, sbs, tots, lane);
        ksphase(sl, v, sbl, totl, lane);
        ksphase(sg, v, sbg, totg, lane);

        float es = fmaf(ss.pw, Ss, sbs);
        float el = fmaf(sl.pw, Sl, sbl);
        float eg = fmaf(sg.pw, Sg, sbg);
        Ss = fmaf(ss.w6, Ss, tots);
        Sl = fmaf(sl.w6, Sl, totl);
        Sg = fmaf(sg.w6, Sg, totg);

        float m0, m1, m2, m3, g0, g1, g2, g3;
        RSTEP(v.x, m0, g0);
        RSTEP(v.y, m1, g1);
        RSTEP(v.z, m2, g2);
        RSTEP(v.w, m3, g3);

        // Perfectly coalesced: warp's float4 stores cover 4 full 128B lines.
        *(float4*)(om + base) = make_float4(m0, m1, m2, m3);
        *(float4*)(og + base) = make_float4(g0, g1, g2, g3);
        *(float4*)(oh + base) = make_float4(m0 - g0, m1 - g1, m2 - g2, m3 - g3);
    }
}

extern "C" void kernel_launch(void* const* d_in, const int* in_sizes, int n_in,
                              void* d_out, int out_size)
{
    const float* x  = (const float*)d_in[0];
    const int*   ps = (const int*)d_in[1];
    const int*   pl = (const int*)d_in[2];
    const int*   pg = (const int*)d_in[3];

    const int B = in_sizes[0] / T_;
    float* out = (float*)d_out;

    const int total_warps = B * SPANS;
    const int blocks = (total_warps + WPC - 1) / WPC;

    macd_scan<<<blocks, 32 * WPC>>>(x, ps, pl, pg, out, B);
}

// round 15
// speedup vs baseline: 1.2119x; 1.2119x over previous
#include <cuda_runtime.h>

#define T_    16384
#define TILE  256              // elements per warp-tile (8 per lane)
#define SPAN  2048             // output elements per warp
#define SPANS (T_ / SPAN)      // 8 warps per row
#define MT    (SPAN / TILE)    // 8 main tiles per warp
#define WPC   4
#define FULL  0xffffffffu

struct Ser { float b, w1, w2, w3, w4, w5, w6, pw, iw1; };

__device__ __forceinline__ Ser make_ser(float b, int lane) {
    Ser s; s.b = b;
    float b2 = b * b, b4 = b2 * b2;
    s.w1 = b4 * b4;          // b^8
    s.w2 = s.w1 * s.w1;      // b^16
    s.w3 = s.w2 * s.w2;      // b^32
    s.w4 = s.w3 * s.w3;      // b^64
    s.w5 = s.w4 * s.w4;      // b^128
    s.w6 = s.w5 * s.w5;      // b^256 (whole-tile carry weight)
    s.iw1 = __fdividef(1.f, s.w1);   // b^-8 (sb-shuffle elimination)
    float pw = 1.f, p = s.w1;
#pragma unroll
    for (int k = 0; k < 5; ++k) { if (lane & (1 << k)) pw *= p; p *= p; }
    s.pw = pw;               // b^(8*lane)
    return s;
}

// Inclusive affine EMA scan over a 256-elt tile (8 per lane).
// sb-shuffle eliminated: entry prefix = (Bv_final - B0) * b^-8, which is
// exactly shfl_up(Bv,1) (and exactly 0 for lane 0 — no predicate needed).
// Carry update S <- b^256*S + tot stays off the reconstruct path.
__device__ __forceinline__ void scan8(const Ser s, const float ax[8],
                                      float y[8], float& S, int lane)
{
    float B0 = ax[0];
#pragma unroll
    for (int i = 1; i < 8; ++i) B0 = fmaf(s.b, B0, ax[i]);
    float Bv = B0;
    float t;
    t = __shfl_up_sync(FULL, Bv, 1);  if (lane >= 1)  Bv = fmaf(s.w1, t, Bv);
    t = __shfl_up_sync(FULL, Bv, 2);  if (lane >= 2)  Bv = fmaf(s.w2, t, Bv);
    t = __shfl_up_sync(FULL, Bv, 4);  if (lane >= 4)  Bv = fmaf(s.w3, t, Bv);
    t = __shfl_up_sync(FULL, Bv, 8);  if (lane >= 8)  Bv = fmaf(s.w4, t, Bv);
    t = __shfl_up_sync(FULL, Bv, 16); if (lane >= 16) Bv = fmaf(s.w5, t, Bv);
    float tot = __shfl_sync(FULL, Bv, 31);
    float e = fmaf(s.pw, S, (Bv - B0) * s.iw1);
#pragma unroll
    for (int i = 0; i < 8; ++i) { e = fmaf(s.b, e, ax[i]); y[i] = e; }
    S = fmaf(s.w6, S, tot);
}

// Carry-only scan (warmup): compose raw x, KS, update carry. No reconstruct.
__device__ __forceinline__ void kstot(const Ser s, const float xv[8],
                                      float& S, int lane)
{
    float Bv = xv[0];
#pragma unroll
    for (int i = 1; i < 8; ++i) Bv = fmaf(s.b, Bv, xv[i]);
    float t;
    t = __shfl_up_sync(FULL, Bv, 1);  if (lane >= 1)  Bv = fmaf(s.w1, t, Bv);
    t = __shfl_up_sync(FULL, Bv, 2);  if (lane >= 2)  Bv = fmaf(s.w2, t, Bv);
    t = __shfl_up_sync(FULL, Bv, 4);  if (lane >= 4)  Bv = fmaf(s.w3, t, Bv);
    t = __shfl_up_sync(FULL, Bv, 8);  if (lane >= 8)  Bv = fmaf(s.w4, t, Bv);
    t = __shfl_up_sync(FULL, Bv, 16); if (lane >= 16) Bv = fmaf(s.w5, t, Bv);
    S = fmaf(s.w6, S, __shfl_sync(FULL, Bv, 31));
}

__device__ __forceinline__ void load8(float v[8], const float* __restrict__ p) {
    const float4 a = *(const float4*)p;
    const float4 b = *(const float4*)(p + 4);
    v[0]=a.x; v[1]=a.y; v[2]=a.z; v[3]=a.w;
    v[4]=b.x; v[5]=b.y; v[6]=b.z; v[7]=b.w;
}

__global__ __launch_bounds__(32 * WPC)
void macd_scan(const float* __restrict__ x,
               const int* __restrict__ ps_, const int* __restrict__ pl_,
               const int* __restrict__ pg_,
               float* __restrict__ out, int B)
{
    const int lane = threadIdx.x & 31;
    const int w    = blockIdx.x * WPC + (threadIdx.x >> 5);
    const int row  = w / SPANS;
    const int span = w - row * SPANS;
    if (row >= B) return;

    const float a_s = 2.f / (float)(ps_[0] + 1), b_s = 1.f - a_s;
    const float a_l = 2.f / (float)(pl_[0] + 1), b_l = 1.f - a_l;
    const float a_g = 2.f / (float)(pg_[0] + 1), b_g = 1.f - a_g;
    const Ser ss = make_ser(b_s, lane);
    const Ser sl = make_ser(b_l, lane);
    const Ser sg = make_ser(b_g, lane);

    const size_t rbase = (size_t)row * T_;
    const int    off0  = span * SPAN;
    const size_t N     = (size_t)B * T_;
    const float* __restrict__ xp = x + rbase;
    float* __restrict__ om = out;
    float* __restrict__ og = out + N;
    float* __restrict__ oh = out + 2 * N;

    float Ss, Sl, Sg;

    if (span == 0) {
        // Exact init: S = x0 makes the first step an identity; sig starts 0.
        const float x0 = __ldg(xp);
        Ss = x0; Sl = x0; Sg = 0.f;
    } else {
        // PF carry-only warmup over [off0-256, off0): three scans of RAW x
        // (unnormalized F-states), no reconstructs, then convert to the
        // cascade carries via the validated partial-fraction identities.
        const float r_s = __fdividef(1.f, b_g - b_s);
        const float r_l = __fdividef(1.f, b_g - b_l);
        const float K_s = -a_g * a_s * b_s * r_s;
        const float K_l =  a_g * a_l * b_l * r_l;
        const float K_g =  a_g * b_g * (a_s * r_s - a_l * r_l);
        const float sg_c = __fdividef(b_s * r_s - b_l * r_l,
                                      b_g * (a_s * r_s - a_l * r_l));

        float wv[8];
        load8(wv, xp + (off0 - TILE) + lane * 8);
        const float x0 = __shfl_sync(FULL, wv[0], 0);
        float Fs = x0 * __fdividef(1.f, a_s);
        float Fl = x0 * __fdividef(1.f, a_l);
        float Fg = x0 * sg_c;
        kstot(ss, wv, Fs, lane);
        kstot(sl, wv, Fl, lane);
        kstot(sg, wv, Fg, lane);
        // Convert F-carries -> cascade (normalized) carries.
        Ss = a_s * Fs;
        Sl = a_l * Fl;
        Sg = fmaf(K_s, Fs, fmaf(K_l, Fl, K_g * Fg));
    }

#pragma unroll 2
    for (int t = 0; t < MT; ++t) {
        const size_t base = rbase + (size_t)off0 + t * TILE + lane * 8;
        float xv[8];
        load8(xv, x + base);
        float axs[8], axl[8], ys[8], yl[8];
#pragma unroll
        for (int i = 0; i < 8; ++i) { axs[i] = a_s * xv[i]; axl[i] = a_l * xv[i]; }
        scan8(ss, axs, ys, Ss, lane);
        scan8(sl, axl, yl, Sl, lane);
        float m[8], axg[8], yg[8];
#pragma unroll
        for (int i = 0; i < 8; ++i) { m[i] = ys[i] - yl[i]; axg[i] = a_g * m[i]; }
        scan8(sg, axg, yg, Sg, lane);

        *(float4*)(om + base)     = make_float4(m[0], m[1], m[2], m[3]);
        *(float4*)(om + base + 4) = make_float4(m[4], m[5], m[6], m[7]);
        *(float4*)(og + base)     = make_float4(yg[0], yg[1], yg[2], yg[3]);
        *(float4*)(og + base + 4) = make_float4(yg[4], yg[5], yg[6], yg[7]);
        *(float4*)(oh + base)     = make_float4(m[0] - yg[0], m[1] - yg[1],
                                                m[2] - yg[2], m[3] - yg[3]);
        *(float4*)(oh + base + 4) = make_float4(m[4] - yg[4], m[5] - yg[5],
                                                m[6] - yg[6], m[7] - yg[7]);
    }
}

extern "C" void kernel_launch(void* const* d_in, const int* in_sizes, int n_in,
                              void* d_out, int out_size)
{
    const float* x  = (const float*)d_in[0];
    const int*   ps = (const int*)d_in[1];
    const int*   pl = (const int*)d_in[2];
    const int*   pg = (const int*)d_in[3];

    const int B = in_sizes[0] / T_;
    float* out = (float*)d_out;

    const int total_warps = B * SPANS;
    const int blocks = (total_warps + WPC - 1) / WPC;

    macd_scan<<<blocks, 32 * WPC>>>(x, ps, pl, pg, out, B);
}